// round 11
// baseline (speedup 1.0000x reference)
#include <cuda_runtime.h>
#include <math.h>

#define Bb 128
#define Tt 100
#define Ff 64
#define ROWP 66   // padded row: [0]=0, [1..64]=data, [65]=0

// Inter-phase buffers (device globals: allocation-free).
__device__ float g_enc2[(size_t)Tt * Bb * 32 * Ff];  // enc layer1 hidden sequence [t][b][ch][pos]
__device__ float g_h1[Bb * 16 * Ff], g_c1[Bb * 16 * Ff];  // enc layer0 final states
__device__ float g_h2[Bb * 32 * Ff], g_c2[Bb * 32 * Ff];  // enc layer1 final states

__device__ __forceinline__ float sigmoidf_(float x) { return 1.0f / (1.0f + expf(-x)); }

// Accumulate gates over `nrows` input rows.
// wp0 points at wq[(rg*CTOT + ci0)*3]; weights packed as float4 = (i,f,o,g) gates.
// soff3 = 8*CTOT*3 advances hc by 8 (per owned state s).
template<int S>
__device__ __forceinline__ void accum_rows(float4 acc[S], const float* __restrict__ rows,
                                           int nrows, const float4* __restrict__ wp0,
                                           int soff3, int pos)
{
#pragma unroll 2
    for (int r = 0; r < nrows; ++r) {
        const float* row = rows + r * ROWP + pos;
        const float x0 = row[0], x1 = row[1], x2 = row[2];
        const float4* wr = wp0 + r * 3;
#pragma unroll
        for (int s = 0; s < S; ++s) {
            const float4 w0 = wr[0], w1 = wr[1], w2 = wr[2];
            float4 a = acc[s];
            a.x = fmaf(w0.x, x0, a.x); a.y = fmaf(w0.y, x0, a.y);
            a.z = fmaf(w0.z, x0, a.z); a.w = fmaf(w0.w, x0, a.w);
            a.x = fmaf(w1.x, x1, a.x); a.y = fmaf(w1.y, x1, a.y);
            a.z = fmaf(w1.z, x1, a.z); a.w = fmaf(w1.w, x1, a.w);
            a.x = fmaf(w2.x, x2, a.x); a.y = fmaf(w2.y, x2, a.y);
            a.z = fmaf(w2.z, x2, a.z); a.w = fmaf(w2.w, x2, a.w);
            acc[s] = a;
            wr += soff3;
        }
    }
}

// One ConvLSTM layer timestep. Each thread owns S states (hc = rg + 8*s, all at `pos`).
// c[] lives in the owner thread's registers across the whole time loop.
template<int S, int CH, int CIN, bool WG>
__device__ __forceinline__ void lstm_step(const float* __restrict__ inrows,
                                          const float* __restrict__ hcur,
                                          float* __restrict__ hnxt,
                                          const float* __restrict__ wq_f,
                                          const float* __restrict__ bq_f,
                                          float* __restrict__ c,
                                          int pos, int rg,
                                          float* __restrict__ gout)
{
    constexpr int CTOT = CIN + CH;
    const float4* wq = (const float4*)wq_f;
    const float4* bq = (const float4*)bq_f;
    float4 acc[S];
#pragma unroll
    for (int s = 0; s < S; ++s) acc[s] = bq[rg + 8 * s];

    accum_rows<S>(acc, inrows, CIN, wq + (rg * CTOT + 0) * 3,   8 * CTOT * 3, pos);
    accum_rows<S>(acc, hcur,   CH,  wq + (rg * CTOT + CIN) * 3, 8 * CTOT * 3, pos);

#pragma unroll
    for (int s = 0; s < S; ++s) {
        const int hc = rg + 8 * s;
        float ig = sigmoidf_(acc[s].x);
        float fg = sigmoidf_(acc[s].y);
        float og = sigmoidf_(acc[s].z);
        float gg = tanhf(acc[s].w);
        float cn = fg * c[s] + ig * gg;
        c[s] = cn;
        float h = og * tanhf(cn);
        hnxt[hc * ROWP + 1 + pos] = h;
        if (WG) gout[hc * Ff + pos] = h;
    }
}

// ---------------- Encoder: enc0 (16h) + enc1 (32h), fused per timestep ----------------
__global__ void __launch_bounds__(512, 1)
enc_kernel(const float* __restrict__ x,
           const float* __restrict__ w0g, const float* __restrict__ b0g,
           const float* __restrict__ w1g, const float* __restrict__ b1g)
{
    extern __shared__ float sm[];
    float* sw0  = sm;                      // [16][17][3][4] = 3264
    float* sb0  = sw0 + 16 * 17 * 12;      // [16][4]        = 64
    float* sw1  = sb0 + 64;                // [32][48][3][4] = 18432
    float* sb1  = sw1 + 32 * 48 * 12;      // [32][4]        = 128
    float* xrow = sb1 + 128;               // 66
    float* h0b  = xrow + ROWP;             // 2*16*66
    float* h1b  = h0b + 2 * 16 * ROWP;     // 2*32*66

    const int tid = threadIdx.x, b = blockIdx.x;
    const int rg = tid >> 6, pos = tid & 63;

    // Stage weights into SMEM, gate-packed: wq[hc][ci][dk] = float4(i,f,o,g), kw=1 slice only.
    for (int i = tid; i < 16 * 17 * 12; i += 512) {
        int g = i & 3, dk = (i >> 2) % 3, ci = (i / 12) % 17, hc = i / (12 * 17);
        sw0[i] = w0g[((g * 16 + hc) * 17 + ci) * 9 + dk * 3 + 1];
    }
    for (int i = tid; i < 64; i += 512) sb0[i] = b0g[(i & 3) * 16 + (i >> 2)];
    for (int i = tid; i < 32 * 48 * 12; i += 512) {
        int g = i & 3, dk = (i >> 2) % 3, ci = (i / 12) % 48, hc = i / (12 * 48);
        sw1[i] = w1g[((g * 32 + hc) * 48 + ci) * 9 + dk * 3 + 1];
    }
    for (int i = tid; i < 128; i += 512) sb1[i] = b1g[(i & 3) * 32 + (i >> 2)];
    for (int i = tid; i < 2 * 16 * ROWP; i += 512) h0b[i] = 0.f;
    for (int i = tid; i < 2 * 32 * ROWP; i += 512) h1b[i] = 0.f;
    if (tid == 0) { xrow[0] = 0.f; xrow[ROWP - 1] = 0.f; }

    float c0r[2] = {0.f, 0.f};
    float c1r[4] = {0.f, 0.f, 0.f, 0.f};

    const float* xb = x + (size_t)b * Tt * Ff;
    int cur = 0;
    for (int t = 0; t < Tt; ++t) {
        if (tid < 64) xrow[1 + tid] = xb[t * Ff + tid];
        __syncthreads();
        lstm_step<2, 16, 1, false>(xrow, h0b + cur * 16 * ROWP, h0b + (cur ^ 1) * 16 * ROWP,
                                   sw0, sb0, c0r, pos, rg, nullptr);
        __syncthreads();
        lstm_step<4, 32, 16, true>(h0b + (cur ^ 1) * 16 * ROWP,
                                   h1b + cur * 32 * ROWP, h1b + (cur ^ 1) * 32 * ROWP,
                                   sw1, sb1, c1r, pos, rg,
                                   g_enc2 + ((size_t)t * Bb + b) * 32 * Ff);
        cur ^= 1;
    }
    __syncthreads();
    // Final states -> global (each thread writes only states it owns).
#pragma unroll
    for (int s = 0; s < 2; ++s) {
        int hc = rg + 8 * s;
        g_h1[((size_t)b * 16 + hc) * Ff + pos] = h0b[cur * 16 * ROWP + hc * ROWP + 1 + pos];
        g_c1[((size_t)b * 16 + hc) * Ff + pos] = c0r[s];
    }
#pragma unroll
    for (int s = 0; s < 4; ++s) {
        int hc = rg + 8 * s;
        g_h2[((size_t)b * 32 + hc) * Ff + pos] = h1b[cur * 32 * ROWP + hc * ROWP + 1 + pos];
        g_c2[((size_t)b * 32 + hc) * Ff + pos] = c1r[s];
    }
}

// ---------------- Decoder: dec0 (32h) + dec1 (16h) + 1x1 conv, fused per timestep ------
__global__ void __launch_bounds__(512, 1)
dec_kernel(const float* __restrict__ wd0g, const float* __restrict__ bd0g,
           const float* __restrict__ wd1g, const float* __restrict__ bd1g,
           const float* __restrict__ fcw, const float* __restrict__ fcb,
           float* __restrict__ out)
{
    extern __shared__ float sm[];
    float* swd0 = sm;                      // [32][64][3][4] = 24576
    float* sbd0 = swd0 + 32 * 64 * 12;     // 128
    float* swd1 = sbd0 + 128;              // [16][48][3][4] = 9216
    float* sbd1 = swd1 + 16 * 48 * 12;     // 64
    float* inr  = sbd1 + 64;               // 32*66
    float* hd0b = inr + 32 * ROWP;         // 2*32*66
    float* hd1b = hd0b + 2 * 32 * ROWP;    // 2*16*66
    float* sfc  = hd1b + 2 * 16 * ROWP;    // 17

    const int tid = threadIdx.x, b = blockIdx.x;
    const int rg = tid >> 6, pos = tid & 63;

    for (int i = tid; i < 32 * 64 * 12; i += 512) {
        int g = i & 3, dk = (i >> 2) % 3, ci = (i / 12) % 64, hc = i / (12 * 64);
        swd0[i] = wd0g[((g * 32 + hc) * 64 + ci) * 9 + dk * 3 + 1];
    }
    for (int i = tid; i < 128; i += 512) sbd0[i] = bd0g[(i & 3) * 32 + (i >> 2)];
    for (int i = tid; i < 16 * 48 * 12; i += 512) {
        int g = i & 3, dk = (i >> 2) % 3, ci = (i / 12) % 48, hc = i / (12 * 48);
        swd1[i] = wd1g[((g * 16 + hc) * 48 + ci) * 9 + dk * 3 + 1];
    }
    for (int i = tid; i < 64; i += 512) sbd1[i] = bd1g[(i & 3) * 16 + (i >> 2)];
    if (tid < 16) sfc[tid] = fcw[tid];
    if (tid == 16) sfc[16] = fcb[0];
    for (int i = tid; i < 32 * ROWP; i += 512) inr[i] = 0.f;
    for (int i = tid; i < 2 * 32 * ROWP; i += 512) hd0b[i] = 0.f;
    for (int i = tid; i < 2 * 16 * ROWP; i += 512) hd1b[i] = 0.f;
    __syncthreads();  // zeroing done before interior fills below

    // Decoder initial states = encoder final states.
    float cd0r[4], cd1r[2];
#pragma unroll
    for (int s = 0; s < 4; ++s) {
        int hc = rg + 8 * s;
        hd0b[hc * ROWP + 1 + pos] = g_h2[((size_t)b * 32 + hc) * Ff + pos];
        cd0r[s] = g_c2[((size_t)b * 32 + hc) * Ff + pos];
    }
#pragma unroll
    for (int s = 0; s < 2; ++s) {
        int hc = rg + 8 * s;
        hd1b[hc * ROWP + 1 + pos] = g_h1[((size_t)b * 16 + hc) * Ff + pos];
        cd1r[s] = g_c1[((size_t)b * 16 + hc) * Ff + pos];
    }

    int cur = 0;
    for (int t = 0; t < Tt; ++t) {
        // Stage enc2[t][b] (dec0 input) into padded SMEM rows.
        const float* src = g_enc2 + ((size_t)t * Bb + b) * 32 * Ff;
        for (int i = tid; i < 32 * Ff; i += 512)
            inr[(i >> 6) * ROWP + 1 + (i & 63)] = src[i];
        __syncthreads();
        lstm_step<4, 32, 32, false>(inr, hd0b + cur * 32 * ROWP, hd0b + (cur ^ 1) * 32 * ROWP,
                                    swd0, sbd0, cd0r, pos, rg, nullptr);
        __syncthreads();
        lstm_step<2, 16, 32, false>(hd0b + (cur ^ 1) * 32 * ROWP,
                                    hd1b + cur * 16 * ROWP, hd1b + (cur ^ 1) * 16 * ROWP,
                                    swd1, sbd1, cd1r, pos, rg, nullptr);
        __syncthreads();
        if (tid < 64) {
            float acc = sfc[16];
            const float* hrow = hd1b + (cur ^ 1) * 16 * ROWP + 1 + tid;
#pragma unroll
            for (int hc = 0; hc < 16; ++hc) acc = fmaf(sfc[hc], hrow[hc * ROWP], acc);
            out[((size_t)b * Tt + t) * Ff + tid] = acc;
        }
        cur ^= 1;
    }
}

extern "C" void kernel_launch(void* const* d_in, const int* in_sizes, int n_in,
                              void* d_out, int out_size)
{
    const float* x      = (const float*)d_in[0];
    const float* enc_w0 = (const float*)d_in[1];
    const float* enc_b0 = (const float*)d_in[2];
    const float* enc_w1 = (const float*)d_in[3];
    const float* enc_b1 = (const float*)d_in[4];
    const float* dec_w0 = (const float*)d_in[5];
    const float* dec_b0 = (const float*)d_in[6];
    const float* dec_w1 = (const float*)d_in[7];
    const float* dec_b1 = (const float*)d_in[8];
    const float* fc_w   = (const float*)d_in[9];
    const float* fc_b   = (const float*)d_in[10];
    float* out = (float*)d_out;

    const int ENC_SM = (16 * 17 * 12 + 64 + 32 * 48 * 12 + 128 + ROWP
                        + 2 * 16 * ROWP + 2 * 32 * ROWP) * 4;          // 113160 B
    const int DEC_SM = (32 * 64 * 12 + 128 + 16 * 48 * 12 + 64 + 32 * ROWP
                        + 2 * 32 * ROWP + 2 * 16 * ROWP + 20) * 4;     // 169808 B

    cudaFuncSetAttribute(enc_kernel, cudaFuncAttributeMaxDynamicSharedMemorySize, ENC_SM);
    cudaFuncSetAttribute(dec_kernel, cudaFuncAttributeMaxDynamicSharedMemorySize, DEC_SM);

    enc_kernel<<<Bb, 512, ENC_SM>>>(x, enc_w0, enc_b0, enc_w1, enc_b1);
    dec_kernel<<<Bb, 512, DEC_SM>>>(dec_w0, dec_b0, dec_w1, dec_b1, fc_w, fc_b, out);
}

// round 12
// speedup vs baseline: 1.6072x; 1.6072x over previous
#include <cuda_runtime.h>
#include <math.h>

#define Bb 128
#define Tt 100
#define Ff 64
#define RP 68   // padded row: [0]=halo0, [1..64]=data, [65]=halo0, [66..67]=pad (16B-aligned rows)

typedef unsigned long long u64;

// Inter-phase buffers (device globals: allocation-free).
__device__ float g_enc2[(size_t)Tt * Bb * 32 * Ff];       // enc layer1 hidden seq [t][b][ch][pos]
__device__ float g_h1[Bb * 16 * Ff], g_c1[Bb * 16 * Ff];  // enc layer0 final states
__device__ float g_h2[Bb * 32 * Ff], g_c2[Bb * 32 * Ff];  // enc layer1 final states

__device__ __forceinline__ u64 ffma2(u64 a, u64 b, u64 c) {
    u64 d;
    asm("fma.rn.f32x2 %0, %1, %2, %3;" : "=l"(d) : "l"(a), "l"(b), "l"(c));
    return d;
}
__device__ __forceinline__ u64 dupf(float x) {
    u64 p; unsigned u = __float_as_uint(x);
    asm("mov.b64 %0, {%1, %2};" : "=l"(p) : "r"(u), "r"(u));
    return p;
}
__device__ __forceinline__ float2 unpk(u64 p) {
    float2 r;
    asm("mov.b64 {%0, %1}, %2;" : "=f"(r.x), "=f"(r.y) : "l"(p));
    return r;
}
__device__ __forceinline__ float sigmoidf_(float x) { return 1.0f / (1.0f + expf(-x)); }

// Accumulate gate pairs over nrows input rows. Weights: ulonglong2 per (hc,ci,tap):
//   .x = (w_i, w_f)  .y = (w_o, w_g).  Inputs duplicated into both f32x2 lanes.
template<int P>
__device__ __forceinline__ void acc_rows(u64* aif, u64* aog,
                                         const float* __restrict__ rows, int nrows,
                                         const ulonglong2* __restrict__ w, int pos0)
{
#pragma unroll 4
    for (int r = 0; r < nrows; ++r) {
        const float* row = rows + r * RP + pos0;   // idx pos0 holds x[pos0-1]
        u64 L[P + 2];
        if constexpr (P == 4) {
            float4 a = *(const float4*)row;        // x[pos0-1 .. pos0+2]
            float2 b = *(const float2*)(row + 4);  // x[pos0+3 .. pos0+4]
            L[0] = dupf(a.x); L[1] = dupf(a.y); L[2] = dupf(a.z); L[3] = dupf(a.w);
            L[4] = dupf(b.x); L[5] = dupf(b.y);
        } else {
            float2 a = *(const float2*)row;        // x[pos0-1 .. pos0]
            float2 b = *(const float2*)(row + 2);  // x[pos0+1 .. pos0+2]
            L[0] = dupf(a.x); L[1] = dupf(a.y); L[2] = dupf(b.x); L[3] = dupf(b.y);
        }
        const ulonglong2 w0 = w[0], w1 = w[1], w2 = w[2];
#pragma unroll
        for (int p = 0; p < P; ++p) {
            aif[p] = ffma2(w0.x, L[p],     aif[p]); aog[p] = ffma2(w0.y, L[p],     aog[p]);
            aif[p] = ffma2(w1.x, L[p + 1], aif[p]); aog[p] = ffma2(w1.y, L[p + 1], aog[p]);
            aif[p] = ffma2(w2.x, L[p + 2], aif[p]); aog[p] = ffma2(w2.y, L[p + 2], aog[p]);
        }
        w += 3;
    }
}

// One ConvLSTM timestep. Thread owns channel hc at positions pos0..pos0+P-1;
// cell state c[P] lives in registers across the whole time loop.
template<int P, int CIN, int CH, bool WG>
__device__ __forceinline__ void lstm_step2(const float* __restrict__ inrows,
                                           const float* __restrict__ hcur,
                                           float* __restrict__ hnxt,
                                           const ulonglong2* __restrict__ wq2,
                                           ulonglong2 bv,
                                           float* __restrict__ c,
                                           int hc, int pos0,
                                           float* __restrict__ gout)
{
    constexpr int CTOT = CIN + CH;
    u64 aif[P], aog[P];
#pragma unroll
    for (int p = 0; p < P; ++p) { aif[p] = bv.x; aog[p] = bv.y; }
    const ulonglong2* w = wq2 + (size_t)hc * CTOT * 3;
    acc_rows<P>(aif, aog, inrows, CIN, w, pos0);
    acc_rows<P>(aif, aog, hcur, CH, w + CIN * 3, pos0);
#pragma unroll
    for (int p = 0; p < P; ++p) {
        float2 xif = unpk(aif[p]), xog = unpk(aog[p]);
        float ig = sigmoidf_(xif.x);
        float fg = sigmoidf_(xif.y);
        float og = sigmoidf_(xog.x);
        float gg = tanhf(xog.y);
        float cn = fg * c[p] + ig * gg;
        c[p] = cn;
        float h = og * tanhf(cn);
        hnxt[hc * RP + 1 + pos0 + p] = h;
        if (WG) gout[hc * Ff + pos0 + p] = h;
    }
}

// ---------------- Encoder: enc0 (16h) + enc1 (32h), fused per timestep ----------------
__global__ void __launch_bounds__(512, 1)
enc_kernel(const float* __restrict__ x,
           const float* __restrict__ w0g, const float* __restrict__ b0g,
           const float* __restrict__ w1g, const float* __restrict__ b1g)
{
    extern __shared__ float sm[];
    float* sw0  = sm;                      // [16][17][3][4] = 3264
    float* sb0  = sw0 + 16 * 17 * 12;      // 64
    float* sw1  = sb0 + 64;                // [32][48][3][4] = 18432
    float* sb1  = sw1 + 32 * 48 * 12;      // 128
    float* xrow = sb1 + 128;               // RP
    float* h0b  = xrow + RP;               // 2*16*RP
    float* h1b  = h0b + 2 * 16 * RP;       // 2*32*RP

    const int tid = threadIdx.x, b = blockIdx.x;

    for (int i = tid; i < 16 * 17 * 12; i += 512) {
        int g = i & 3, dk = (i >> 2) % 3, ci = (i / 12) % 17, hc = i / (12 * 17);
        sw0[i] = w0g[((g * 16 + hc) * 17 + ci) * 9 + dk * 3 + 1];
    }
    for (int i = tid; i < 64; i += 512) sb0[i] = b0g[(i & 3) * 16 + (i >> 2)];
    for (int i = tid; i < 32 * 48 * 12; i += 512) {
        int g = i & 3, dk = (i >> 2) % 3, ci = (i / 12) % 48, hc = i / (12 * 48);
        sw1[i] = w1g[((g * 32 + hc) * 48 + ci) * 9 + dk * 3 + 1];
    }
    for (int i = tid; i < 128; i += 512) sb1[i] = b1g[(i & 3) * 32 + (i >> 2)];
    for (int i = tid; i < 2 * 16 * RP; i += 512) h0b[i] = 0.f;
    for (int i = tid; i < 2 * 32 * RP; i += 512) h1b[i] = 0.f;
    if (tid == 0) { xrow[0] = 0.f; xrow[65] = 0.f; xrow[66] = 0.f; xrow[67] = 0.f; }
    __syncthreads();

    const int hc0 = tid >> 5, pp0 = (tid & 31) * 2;   // layer0: P=2, 16 ch
    const int hc1 = tid >> 4, pp1 = (tid & 15) * 4;   // layer1: P=4, 32 ch
    const ulonglong2 b0v = ((const ulonglong2*)sb0)[hc0];
    const ulonglong2 b1v = ((const ulonglong2*)sb1)[hc1];
    float c0[2] = {0.f, 0.f};
    float c1[4] = {0.f, 0.f, 0.f, 0.f};

    const float* xb = x + (size_t)b * Tt * Ff;
    int cur = 0;
    for (int t = 0; t < Tt; ++t) {
        if (tid < 64) xrow[1 + tid] = xb[t * Ff + tid];
        __syncthreads();
        lstm_step2<2, 1, 16, false>(xrow, h0b + cur * 16 * RP, h0b + (cur ^ 1) * 16 * RP,
                                    (const ulonglong2*)sw0, b0v, c0, hc0, pp0, nullptr);
        __syncthreads();
        lstm_step2<4, 16, 32, true>(h0b + (cur ^ 1) * 16 * RP,
                                    h1b + cur * 32 * RP, h1b + (cur ^ 1) * 32 * RP,
                                    (const ulonglong2*)sw1, b1v, c1, hc1, pp1,
                                    g_enc2 + ((size_t)t * Bb + b) * 32 * Ff);
        cur ^= 1;
    }
    __syncthreads();
#pragma unroll
    for (int p = 0; p < 2; ++p) {
        g_h1[((size_t)b * 16 + hc0) * Ff + pp0 + p] = h0b[cur * 16 * RP + hc0 * RP + 1 + pp0 + p];
        g_c1[((size_t)b * 16 + hc0) * Ff + pp0 + p] = c0[p];
    }
#pragma unroll
    for (int p = 0; p < 4; ++p) {
        g_h2[((size_t)b * 32 + hc1) * Ff + pp1 + p] = h1b[cur * 32 * RP + hc1 * RP + 1 + pp1 + p];
        g_c2[((size_t)b * 32 + hc1) * Ff + pp1 + p] = c1[p];
    }
}

// ---------------- Decoder: dec0 (32h) + dec1 (16h) + 1x1 conv, fused per timestep ------
__global__ void __launch_bounds__(512, 1)
dec_kernel(const float* __restrict__ wd0g, const float* __restrict__ bd0g,
           const float* __restrict__ wd1g, const float* __restrict__ bd1g,
           const float* __restrict__ fcw, const float* __restrict__ fcb,
           float* __restrict__ out)
{
    extern __shared__ float sm[];
    float* swd0 = sm;                      // [32][64][3][4] = 24576
    float* sbd0 = swd0 + 32 * 64 * 12;     // 128
    float* swd1 = sbd0 + 128;              // [16][48][3][4] = 9216
    float* sbd1 = swd1 + 16 * 48 * 12;     // 64
    float* inr  = sbd1 + 64;               // 32*RP
    float* hd0b = inr + 32 * RP;           // 2*32*RP
    float* hd1b = hd0b + 2 * 32 * RP;      // 2*16*RP
    float* sfc  = hd1b + 2 * 16 * RP;      // 20

    const int tid = threadIdx.x, b = blockIdx.x;

    for (int i = tid; i < 32 * 64 * 12; i += 512) {
        int g = i & 3, dk = (i >> 2) % 3, ci = (i / 12) % 64, hc = i / (12 * 64);
        swd0[i] = wd0g[((g * 32 + hc) * 64 + ci) * 9 + dk * 3 + 1];
    }
    for (int i = tid; i < 128; i += 512) sbd0[i] = bd0g[(i & 3) * 32 + (i >> 2)];
    for (int i = tid; i < 16 * 48 * 12; i += 512) {
        int g = i & 3, dk = (i >> 2) % 3, ci = (i / 12) % 48, hc = i / (12 * 48);
        swd1[i] = wd1g[((g * 16 + hc) * 48 + ci) * 9 + dk * 3 + 1];
    }
    for (int i = tid; i < 64; i += 512) sbd1[i] = bd1g[(i & 3) * 16 + (i >> 2)];
    if (tid < 16) sfc[tid] = fcw[tid];
    if (tid == 16) sfc[16] = fcb[0];
    for (int i = tid; i < 32 * RP; i += 512) inr[i] = 0.f;
    for (int i = tid; i < 2 * 32 * RP; i += 512) hd0b[i] = 0.f;
    for (int i = tid; i < 2 * 16 * RP; i += 512) hd1b[i] = 0.f;
    __syncthreads();   // zero pass done before interior fills

    const int hcA = tid >> 4, ppA = (tid & 15) * 4;   // dec0: P=4, 32 ch
    const int hcB = tid >> 5, ppB = (tid & 31) * 2;   // dec1: P=2, 16 ch
    const ulonglong2 b0v = ((const ulonglong2*)sbd0)[hcA];
    const ulonglong2 b1v = ((const ulonglong2*)sbd1)[hcB];

    // Decoder initial states = encoder final states (owner-thread fills).
    float cd0[4], cd1[2];
#pragma unroll
    for (int p = 0; p < 4; ++p) {
        hd0b[hcA * RP + 1 + ppA + p] = g_h2[((size_t)b * 32 + hcA) * Ff + ppA + p];
        cd0[p] = g_c2[((size_t)b * 32 + hcA) * Ff + ppA + p];
    }
#pragma unroll
    for (int p = 0; p < 2; ++p) {
        hd1b[hcB * RP + 1 + ppB + p] = g_h1[((size_t)b * 16 + hcB) * Ff + ppB + p];
        cd1[p] = g_c1[((size_t)b * 16 + hcB) * Ff + ppB + p];
    }

    int cur = 0;
    for (int t = 0; t < Tt; ++t) {
        const float* src = g_enc2 + ((size_t)t * Bb + b) * 32 * Ff;
        for (int i = tid; i < 32 * Ff; i += 512)
            inr[(i >> 6) * RP + 1 + (i & 63)] = src[i];
        __syncthreads();
        lstm_step2<4, 32, 32, false>(inr, hd0b + cur * 32 * RP, hd0b + (cur ^ 1) * 32 * RP,
                                     (const ulonglong2*)swd0, b0v, cd0, hcA, ppA, nullptr);
        __syncthreads();
        lstm_step2<2, 32, 16, false>(hd0b + (cur ^ 1) * 32 * RP,
                                     hd1b + cur * 16 * RP, hd1b + (cur ^ 1) * 16 * RP,
                                     (const ulonglong2*)swd1, b1v, cd1, hcB, ppB, nullptr);
        __syncthreads();
        if (tid < 64) {
            float acc = sfc[16];
            const float* hrow = hd1b + (cur ^ 1) * 16 * RP + 1 + tid;
#pragma unroll
            for (int hc = 0; hc < 16; ++hc) acc = fmaf(sfc[hc], hrow[hc * RP], acc);
            out[((size_t)b * Tt + t) * Ff + tid] = acc;
        }
        cur ^= 1;
    }
}

extern "C" void kernel_launch(void* const* d_in, const int* in_sizes, int n_in,
                              void* d_out, int out_size)
{
    const float* x      = (const float*)d_in[0];
    const float* enc_w0 = (const float*)d_in[1];
    const float* enc_b0 = (const float*)d_in[2];
    const float* enc_w1 = (const float*)d_in[3];
    const float* enc_b1 = (const float*)d_in[4];
    const float* dec_w0 = (const float*)d_in[5];
    const float* dec_b0 = (const float*)d_in[6];
    const float* dec_w1 = (const float*)d_in[7];
    const float* dec_b1 = (const float*)d_in[8];
    const float* fc_w   = (const float*)d_in[9];
    const float* fc_b   = (const float*)d_in[10];
    float* out = (float*)d_out;

    const int ENC_SM = (16 * 17 * 12 + 64 + 32 * 48 * 12 + 128 + RP
                        + 2 * 16 * RP + 2 * 32 * RP) * 4;
    const int DEC_SM = (32 * 64 * 12 + 128 + 16 * 48 * 12 + 64 + 32 * RP
                        + 2 * 32 * RP + 2 * 16 * RP + 20) * 4;

    cudaFuncSetAttribute(enc_kernel, cudaFuncAttributeMaxDynamicSharedMemorySize, ENC_SM);
    cudaFuncSetAttribute(dec_kernel, cudaFuncAttributeMaxDynamicSharedMemorySize, DEC_SM);

    enc_kernel<<<Bb, 512, ENC_SM>>>(x, enc_w0, enc_b0, enc_w1, enc_b1);
    dec_kernel<<<Bb, 512, DEC_SM>>>(dec_w0, dec_b0, dec_w1, dec_b1, fc_w, fc_b, out);
}